// round 12
// baseline (speedup 1.0000x reference)
#include <cuda_runtime.h>
#include <cstdint>

#define B_ 4
#define C_ 3
#define T_ 103
#define H_ 224
#define W_ 224
#define HW_ (H_ * W_)
#define W4_ (W_ / 4)          // 56 float4 per row
#define NBT (B_ * T_)         // 412

// Predicated 128-bit load: value if pred, else zeros. No branch.
__device__ __forceinline__ float4 ldg128_pred(const float* p, int pred) {
    float4 v = make_float4(0.f, 0.f, 0.f, 0.f);
    asm volatile("{\n\t"
                 ".reg .pred lp;\n\t"
                 "setp.ne.b32 lp, %4, 0;\n\t"
                 "@lp ld.global.nc.v4.f32 {%0,%1,%2,%3}, [%5];\n\t"
                 "}"
                 : "+f"(v.x), "+f"(v.y), "+f"(v.z), "+f"(v.w)
                 : "r"(pred), "l"(p));
    return v;
}

// Predicated L2 prefetch: no destination register, no scoreboard —
// raises memory-level parallelism without register pressure.
__device__ __forceinline__ void prefetch_l2_pred(const float* p, int pred) {
    asm volatile("{\n\t"
                 ".reg .pred lp;\n\t"
                 "setp.ne.b32 lp, %0, 0;\n\t"
                 "@lp prefetch.global.L2 [%1];\n\t"
                 "}"
                 :: "r"(pred), "l"(p));
}

// Streaming 128-bit store (evict-first: output is never re-read).
__device__ __forceinline__ void stg128_cs(float* p, float4 v) {
    asm volatile("st.global.cs.v4.f32 [%0], {%1,%2,%3,%4};"
                 :: "l"(p), "f"(v.x), "f"(v.y), "f"(v.z), "f"(v.w)
                 : "memory");
}

__global__ __launch_bounds__(224)
void fuse_kernel(const float* __restrict__ video,
                 const float* __restrict__ bbox,
                 const int* __restrict__ index,
                 float* __restrict__ out)
{
    const int bt = blockIdx.y;               // b*T + t
    const int b  = bt / T_;
    const int t  = bt % T_;

    __shared__ int s_cx0, s_cxr, s_cy0, s_cyr;   // own rect: lo + range
    __shared__ int s_bx0, s_bxr, s_by0, s_byr;   // perm br rect: lo + range
    __shared__ int s_bp;

    if (threadIdx.x == 0 && threadIdx.y == 0) {
        const int bp = index[b];
        s_bp = bp;
        const float* bb = bbox + ((size_t)b * T_ + t) * 8;
        float xmin = fminf(fminf(bb[0], bb[2]), fminf(bb[4], bb[6]));
        float xmax = fmaxf(fmaxf(bb[0], bb[2]), fmaxf(bb[4], bb[6]));
        float ymin = fminf(fminf(bb[1], bb[3]), fminf(bb[5], bb[7]));
        float ymax = fmaxf(fmaxf(bb[1], bb[3]), fmaxf(bb[5], bb[7]));
        const int cx0 = (int)fmaxf(xmin, 0.0f);
        const int cy0 = (int)fmaxf(ymin, 0.0f);
        const int cx1 = (int)fminf(xmax, (float)W_);
        const int cy1 = (int)fminf(ymax, (float)H_);
        s_cx0 = cx0; s_cxr = cx1 - cx0;
        s_cy0 = cy0; s_cyr = cy1 - cy0;

        const float* bbp = bbox + ((size_t)bp * T_ + t) * 8;
        const int bx0 = (int)fminf(fminf(bbp[0], bbp[2]), fminf(bbp[4], bbp[6]));
        const int bx1 = (int)fmaxf(fmaxf(bbp[0], bbp[2]), fmaxf(bbp[4], bbp[6]));
        const int by0 = (int)fminf(fminf(bbp[1], bbp[3]), fminf(bbp[5], bbp[7]));
        const int by1 = (int)fmaxf(fmaxf(bbp[1], bbp[3]), fmaxf(bbp[5], bbp[7]));
        s_bx0 = bx0; s_bxr = bx1 - bx0;
        s_by0 = by0; s_byr = by1 - by0;
    }
    __syncthreads();

    const int h = blockIdx.x * 4 + threadIdx.y;   // row 0..223
    const int x = threadIdx.x * 4;                // pixel column

    const bool rowM  = (unsigned)(h - s_cy0) <= (unsigned)s_cyr;
    const bool rowBr = (unsigned)(h - s_by0) <= (unsigned)s_byr;
    const float frB  = rowBr ? 1.0f : 0.0f;

    // Blend coefficients, computed once, reused for 3 channels.
    float fm[4], u[4];
    bool anyM = false, anyBg = false;
#pragma unroll
    for (int i = 0; i < 4; i++) {
        const int xi = x + i;
        const bool mi  = rowM & ((unsigned)(xi - s_cx0) <= (unsigned)s_cxr);
        const bool bri = (unsigned)(xi - s_bx0) <= (unsigned)s_bxr;
        fm[i] = mi ? 1.0f : 0.0f;
        const float a = fmaf(-frB, bri ? 1.0f : 0.0f, 1.0f);  // 1 - frB*fbx
        u[i] = fmaf(-fm[i], a, a);                            // (1-fm)*a
        anyM  |= mi;
        anyBg |= (u[i] != 0.0f);
    }
    const int needOwn  = anyM  ? 1 : 0;
    const int needPerm = anyBg ? 1 : 0;

    const size_t rowOff = (size_t)h * W_ + x;
    const size_t cs     = (size_t)T_ * HW_;     // channel stride
    const float* ownP  = video + ((size_t)(b * C_) * T_ + t) * (size_t)HW_ + rowOff;
    const float* permP = video + ((size_t)(s_bp * C_) * T_ + t) * (size_t)HW_ + rowOff;
    float*       outP  = out   + ((size_t)(b * C_) * T_ + t) * (size_t)HW_ + rowOff;

    // Register-free MLP boost: pull channels 1 and 2 into L2 NOW, so their
    // LDGs below complete as L2 hits while channel 0 streams from DRAM.
    prefetch_l2_pred(ownP  + cs,      needOwn);
    prefetch_l2_pred(permP + cs,      needPerm);
    prefetch_l2_pred(ownP  + 2 * cs,  needOwn);
    prefetch_l2_pred(permP + 2 * cs,  needPerm);

#pragma unroll
    for (int c = 0; c < C_; c++) {
        const float4 own  = ldg128_pred(ownP,  needOwn);
        const float4 perm = ldg128_pred(permP, needPerm);
        float4 r;
        r.x = fmaf(own.x, fm[0], perm.x * u[0]);
        r.y = fmaf(own.y, fm[1], perm.y * u[1]);
        r.z = fmaf(own.z, fm[2], perm.z * u[2]);
        r.w = fmaf(own.w, fm[3], perm.w * u[3]);
        stg128_cs(outP, r);
        ownP  += cs;
        permP += cs;
        outP  += cs;
    }
}

extern "C" void kernel_launch(void* const* d_in, const int* in_sizes, int n_in,
                              void* d_out, int out_size)
{
    const float* video = (const float*)d_in[0];
    const float* bbox  = (const float*)d_in[1];
    const int*   index = (const int*)d_in[2];
    float* out = (float*)d_out;

    dim3 block(W4_, 4);          // 224 threads
    dim3 grid(H_ / 4, NBT);      // (56, 412)
    fuse_kernel<<<grid, block>>>(video, bbox, index, out);
}

// round 16
// speedup vs baseline: 1.0419x; 1.0419x over previous
#include <cuda_runtime.h>
#include <cstdint>

#define B_ 4
#define C_ 3
#define T_ 103
#define H_ 224
#define W_ 224
#define HW_ (H_ * W_)
#define W4_ (W_ / 4)          // 56 float4 per row
#define NBT (B_ * T_)         // 412

// Predicated 128-bit load with L2 evict-first cache-hint policy.
__device__ __forceinline__ float4 ldg128_pred_pol(const float* p, int pred, uint64_t pol) {
    float4 v = make_float4(0.f, 0.f, 0.f, 0.f);
    asm volatile("{\n\t"
                 ".reg .pred lp;\n\t"
                 "setp.ne.b32 lp, %4, 0;\n\t"
                 "@lp ld.global.nc.L2::cache_hint.v4.f32 {%0,%1,%2,%3}, [%5], %6;\n\t"
                 "}"
                 : "+f"(v.x), "+f"(v.y), "+f"(v.z), "+f"(v.w)
                 : "r"(pred), "l"(p), "l"(pol));
    return v;
}

// Streaming 128-bit store (evict-first: output is never re-read).
__device__ __forceinline__ void stg128_cs(float* p, float4 v) {
    asm volatile("st.global.cs.v4.f32 [%0], {%1,%2,%3,%4};"
                 :: "l"(p), "f"(v.x), "f"(v.y), "f"(v.z), "f"(v.w)
                 : "memory");
}

__global__ __launch_bounds__(224)
void fuse_kernel(const float* __restrict__ video,
                 const float* __restrict__ bbox,
                 const int* __restrict__ index,
                 float* __restrict__ out)
{
    const int bt = blockIdx.y;               // b*T + t
    const int b  = bt / T_;
    const int t  = bt % T_;

    __shared__ int s_cx0, s_cxr, s_cy0, s_cyr;   // own rect: lo + range
    __shared__ int s_bx0, s_bxr, s_by0, s_byr;   // perm br rect: lo + range
    __shared__ int s_bp;

    if (threadIdx.x == 0 && threadIdx.y == 0) {
        const int bp = index[b];
        s_bp = bp;
        const float* bb = bbox + ((size_t)b * T_ + t) * 8;
        float xmin = fminf(fminf(bb[0], bb[2]), fminf(bb[4], bb[6]));
        float xmax = fmaxf(fmaxf(bb[0], bb[2]), fmaxf(bb[4], bb[6]));
        float ymin = fminf(fminf(bb[1], bb[3]), fminf(bb[5], bb[7]));
        float ymax = fmaxf(fmaxf(bb[1], bb[3]), fmaxf(bb[5], bb[7]));
        const int cx0 = (int)fmaxf(xmin, 0.0f);
        const int cy0 = (int)fmaxf(ymin, 0.0f);
        const int cx1 = (int)fminf(xmax, (float)W_);
        const int cy1 = (int)fminf(ymax, (float)H_);
        s_cx0 = cx0; s_cxr = cx1 - cx0;
        s_cy0 = cy0; s_cyr = cy1 - cy0;

        const float* bbp = bbox + ((size_t)bp * T_ + t) * 8;
        const int bx0 = (int)fminf(fminf(bbp[0], bbp[2]), fminf(bbp[4], bbp[6]));
        const int bx1 = (int)fmaxf(fmaxf(bbp[0], bbp[2]), fmaxf(bbp[4], bbp[6]));
        const int by0 = (int)fminf(fminf(bbp[1], bbp[3]), fminf(bbp[5], bbp[7]));
        const int by1 = (int)fmaxf(fmaxf(bbp[1], bbp[3]), fmaxf(bbp[5], bbp[7]));
        s_bx0 = bx0; s_bxr = bx1 - bx0;
        s_by0 = by0; s_byr = by1 - by0;
    }
    __syncthreads();

    // Evict-first L2 policy (streaming): created once, reused on all loads.
    uint64_t pol;
    asm volatile("createpolicy.fractional.L2::evict_first.b64 %0, 1.0;" : "=l"(pol));

    const int h = blockIdx.x * 4 + threadIdx.y;   // row 0..223
    const int x = threadIdx.x * 4;                // pixel column

    const bool rowM  = (unsigned)(h - s_cy0) <= (unsigned)s_cyr;
    const bool rowBr = (unsigned)(h - s_by0) <= (unsigned)s_byr;
    const float frB  = rowBr ? 1.0f : 0.0f;

    // Blend coefficients, computed once, reused for 3 channels.
    float fm[4], u[4];
    bool anyM = false, anyBg = false;
#pragma unroll
    for (int i = 0; i < 4; i++) {
        const int xi = x + i;
        const bool mi  = rowM & ((unsigned)(xi - s_cx0) <= (unsigned)s_cxr);
        const bool bri = (unsigned)(xi - s_bx0) <= (unsigned)s_bxr;
        fm[i] = mi ? 1.0f : 0.0f;
        const float a = fmaf(-frB, bri ? 1.0f : 0.0f, 1.0f);  // 1 - frB*fbx
        u[i] = fmaf(-fm[i], a, a);                            // (1-fm)*a
        anyM  |= mi;
        anyBg |= (u[i] != 0.0f);
    }
    const int needOwn  = anyM  ? 1 : 0;
    const int needPerm = anyBg ? 1 : 0;

    const size_t rowOff = (size_t)h * W_ + x;
    const size_t cs     = (size_t)T_ * HW_;     // channel stride
    const float* ownP  = video + ((size_t)(b * C_) * T_ + t) * (size_t)HW_ + rowOff;
    const float* permP = video + ((size_t)(s_bp * C_) * T_ + t) * (size_t)HW_ + rowOff;
    float*       outP  = out   + ((size_t)(b * C_) * T_ + t) * (size_t)HW_ + rowOff;

#pragma unroll
    for (int c = 0; c < C_; c++) {
        const float4 own  = ldg128_pred_pol(ownP,  needOwn,  pol);
        const float4 perm = ldg128_pred_pol(permP, needPerm, pol);
        float4 r;
        r.x = fmaf(own.x, fm[0], perm.x * u[0]);
        r.y = fmaf(own.y, fm[1], perm.y * u[1]);
        r.z = fmaf(own.z, fm[2], perm.z * u[2]);
        r.w = fmaf(own.w, fm[3], perm.w * u[3]);
        stg128_cs(outP, r);
        ownP  += cs;
        permP += cs;
        outP  += cs;
    }
}

extern "C" void kernel_launch(void* const* d_in, const int* in_sizes, int n_in,
                              void* d_out, int out_size)
{
    const float* video = (const float*)d_in[0];
    const float* bbox  = (const float*)d_in[1];
    const int*   index = (const int*)d_in[2];
    float* out = (float*)d_out;

    dim3 block(W4_, 4);          // 224 threads
    dim3 grid(H_ / 4, NBT);      // (56, 412)
    fuse_kernel<<<grid, block>>>(video, bbox, index, out);
}